// round 16
// baseline (speedup 1.0000x reference)
#include <cuda_runtime.h>
#include <cuda_fp16.h>
#include <cstdint>

#define NPTS 500000
#define NCLS 20
#define RPAD 32      // padded row stride in halves (64 B rows, line-aligned)
#define NK   16

// fp16 probs table, 64B rows, 128B-aligned: 32 MB (L2-resident). Zero-initialized
// device global: padding halves [20,32) are never written and stay 0.
__device__ __align__(128) __half g_probs_h[(size_t)NPTS * RPAD];
__device__ float  g_acc[2];    // [0]=sum of mean_dist over valid pts, [1]=valid count
__device__ int    g_done = 0;

// Kernel 1: softmax, smem-staged coalesced loads, padded fp16 rows.
__global__ void softmax_kernel(const float* __restrict__ logits, int rstride) {
    __shared__ float tile[256 * 21];   // 21-float rows -> conflict-free column reads
    if (blockIdx.x == 0 && threadIdx.x == 0) {
        g_acc[0] = 0.0f;
        g_acc[1] = 0.0f;
        g_done   = 0;
    }
    const int rowBase = blockIdx.x * 256;
    const int rowsInBlock = min(256, NPTS - rowBase);
    if (rowsInBlock <= 0) return;

    const float4* s4 = reinterpret_cast<const float4*>(logits + (size_t)rowBase * NCLS);
    const int nvec = rowsInBlock * NCLS / 4;
    for (int i = threadIdx.x; i < nvec; i += 256) {
        float4 v = s4[i];
        int base = i * 4;
        int r = base / NCLS;
        int c = base - r * NCLS;
        float* d = &tile[r * 21 + c];
        d[0] = v.x; d[1] = v.y; d[2] = v.z; d[3] = v.w;
    }
    __syncthreads();

    const int n = rowBase + threadIdx.x;
    if (threadIdx.x >= rowsInBlock) return;
    float* f = &tile[threadIdx.x * 21];

    float m = f[0];
#pragma unroll
    for (int i = 1; i < NCLS; i++) m = fmaxf(m, f[i]);
    float s = 0.0f;
    float e[NCLS];
#pragma unroll
    for (int i = 0; i < NCLS; i++) { e[i] = __expf(f[i] - m); s += e[i]; }
    float inv = 1.0f / s;

    __half2 h[10];
#pragma unroll
    for (int i = 0; i < 10; i++)
        h[i] = __floats2half2_rn(e[2 * i] * inv, e[2 * i + 1] * inv);

    unsigned int* hw = reinterpret_cast<unsigned int*>(h);
    uint4* dst = reinterpret_cast<uint4*>(g_probs_h + (size_t)n * rstride);
    dst[0] = make_uint4(hw[0], hw[1], hw[2], hw[3]);
    dst[1] = make_uint4(hw[4], hw[5], hw[6], hw[7]);
    *reinterpret_cast<uint2*>(dst + 2) = make_uint2(hw[8], hw[9]);
}

// Kernel 2: warp-per-3-points gather (ILP x3), 8 rows per LDG.128, capped at
// 6 blocks/SM (<=42 regs) — the occupancy point where 48 warps x 3 points
// beats 64 warps x 2.
// Lane layout: grp = lane>>2 (0..7), sub = lane&3; every lane loads uint4 of a
// 64B row; padding reads are zeros -> no lane predicate. Invalid neighbors
// self-redirect to the point's own row -> zero distance -> no validity
// predicate in the gather loop.
// Index words: A = points {0,1} (lanes 0-15 / 16-31); B lanes 0-15 = point 2,
// B lanes 16-31 = point 2 again (redirected; its distances are counted once
// via nv2 from the LOW half only).
__global__ void __launch_bounds__(256, 6)
loss_kernel(const int* __restrict__ nbr,
            const int* __restrict__ labels,
            float* __restrict__ out, int rstrideB) {
    const int lane = threadIdx.x & 31;
    const int warpInBlock = threadIdx.x >> 5;
    const int warpsPerBlock = blockDim.x >> 5;
    const int gwarp = blockIdx.x * warpsPerBlock + warpInBlock;
    const int totalWarps = gridDim.x * warpsPerBlock;
    const int grp = lane >> 2;
    const int sub = lane & 3;
    const char* laneBase = reinterpret_cast<const char*>(g_probs_h) + 16 * sub;

    float accTot = 0.0f;
    float cnt    = 0.0f;
    const __half2 z2 = __float2half2_rn(0.f);

    for (int n0 = gwarp; n0 < NPTS; n0 += 3 * totalWarps) {
        const int n1 = n0 + totalWarps;
        const int n2 = n0 + 2 * totalWarps;
        const bool h1 = (n1 < NPTS), h2 = (n2 < NPTS);
        const int s1 = min(n1, NPTS - 1);
        const int s2 = min(n2, NPTS - 1);

        int lab0 = labels[n0];
        int lab1 = h1 ? labels[n1] : -1;
        int lab2 = h2 ? labels[n2] : -1;

        // Index word A: points {0,1}. Word B: point 2 (both halves).
        const int ptA = (lane < 16) ? n0 : s1;
        int ia = nbr[ptA * NK + (lane & 15)];
        int ib = nbr[s2 * NK + (lane & 15)];
        bool va = (ia >= 0), vb = (ib >= 0);
        int offA = (va ? ia : ptA) * rstrideB;
        int offB = (vb ? ib : s2) * rstrideB;

        unsigned vmA = __ballot_sync(0xFFFFFFFFu, va);
        unsigned vmB = __ballot_sync(0xFFFFFFFFu, vb);
        int nv0 = __popc(vmA & 0xFFFFu);
        int nv1 = __popc(vmA >> 16);
        int nv2 = __popc(vmB & 0xFFFFu);

        // Own rows (uint4 per lane; tails read zero padding)
        uint4 p0 = *reinterpret_cast<const uint4*>(laneBase + n0 * rstrideB);
        uint4 p1 = *reinterpret_cast<const uint4*>(laneBase + s1 * rstrideB);
        uint4 p2 = *reinterpret_cast<const uint4*>(laneBase + s2 * rstrideB);
        const __half2* ph0 = reinterpret_cast<const __half2*>(&p0);
        const __half2* ph1 = reinterpret_cast<const __half2*>(&p1);
        const __half2* ph2 = reinterpret_cast<const __half2*>(&p2);

        __half2 acc0 = z2, acc1 = z2, acc2 = z2;
#pragma unroll
        for (int s = 0; s < 2; s++) {
            int o0 = __shfl_sync(0xFFFFFFFFu, offA, 8 * s + grp);
            int o1 = __shfl_sync(0xFFFFFFFFu, offA, 16 + 8 * s + grp);
            int o2 = __shfl_sync(0xFFFFFFFFu, offB, 8 * s + grp);
            uint4 q0 = *reinterpret_cast<const uint4*>(laneBase + o0);
            uint4 q1 = *reinterpret_cast<const uint4*>(laneBase + o1);
            uint4 q2 = *reinterpret_cast<const uint4*>(laneBase + o2);
            const __half2* qh0 = reinterpret_cast<const __half2*>(&q0);
            const __half2* qh1 = reinterpret_cast<const __half2*>(&q1);
            const __half2* qh2 = reinterpret_cast<const __half2*>(&q2);
#pragma unroll
            for (int j = 0; j < 4; j++) {
                __half2 d0 = __hsub2(ph0[j], qh0[j]);
                __half2 d1 = __hsub2(ph1[j], qh1[j]);
                __half2 d2 = __hsub2(ph2[j], qh2[j]);
                acc0 = __hfma2(d0, d0, acc0);
                acc1 = __hfma2(d1, d1, acc1);
                acc2 = __hfma2(d2, d2, acc2);
            }
        }

        // Point 2's neighbors 8..15 (high half of word B)
#pragma unroll
        for (int s = 0; s < 2; s++) {
            int o2 = __shfl_sync(0xFFFFFFFFu, offB, 16 + 8 * s + grp);
            uint4 q2 = *reinterpret_cast<const uint4*>(laneBase + o2);
            const __half2* qh2 = reinterpret_cast<const __half2*>(&q2);
#pragma unroll
            for (int j = 0; j < 4; j++) {
                __half2 d2 = __hsub2(ph2[j], qh2[j]);
                acc2 = __hfma2(d2, d2, acc2);
            }
        }
        // note: nv2 must count ALL 16 neighbors of point 2
        nv2 += __popc(vmB >> 16);

        // Epilogue: validity enters only here (branchless).
        float inv0 = (lab0 != -1 && nv0 > 0) ? __frcp_rn((float)nv0) : 0.0f;
        float inv1 = (h1 && lab1 != -1 && nv1 > 0) ? __frcp_rn((float)nv1) : 0.0f;
        float inv2 = (h2 && lab2 != -1 && nv2 > 0) ? __frcp_rn((float)nv2) : 0.0f;
        float2 a0 = __half22float2(acc0);
        float2 a1 = __half22float2(acc1);
        float2 a2 = __half22float2(acc2);
        accTot = fmaf(a0.x + a0.y, inv0, accTot);
        accTot = fmaf(a1.x + a1.y, inv1, accTot);
        accTot = fmaf(a2.x + a2.y, inv2, accTot);
        cnt += (lab0 != -1 ? 1.0f : 0.0f) + (h1 && lab1 != -1 ? 1.0f : 0.0f)
             + (h2 && lab2 != -1 ? 1.0f : 0.0f);
    }

    // One butterfly reduce per warp
#pragma unroll
    for (int o = 16; o > 0; o >>= 1)
        accTot += __shfl_xor_sync(0xFFFFFFFFu, accTot, o);

    // Block reduce -> one atomic pair per block
    __shared__ float sSum[32];
    __shared__ float sCnt[32];
    if (lane == 0) { sSum[warpInBlock] = accTot; sCnt[warpInBlock] = cnt; }
    __syncthreads();
    if (threadIdx.x == 0) {
        float bs = 0.0f, bc = 0.0f;
        for (int w = 0; w < warpsPerBlock; w++) { bs += sSum[w]; bc += sCnt[w]; }
        atomicAdd(&g_acc[0], bs);
        atomicAdd(&g_acc[1], bc);
        __threadfence();
        int t = atomicAdd(&g_done, 1);
        if (t == gridDim.x - 1) {
            out[0] = g_acc[0] / fmaxf(g_acc[1], 1.0f);  // LOSS_WEIGHT = 1.0
            g_done = 0;
        }
    }
}

extern "C" void kernel_launch(void* const* d_in, const int* in_sizes, int n_in,
                              void* d_out, int out_size) {
    const float* logits = nullptr;
    const int*   nbr    = nullptr;
    const int*   labels = nullptr;
    for (int i = 0; i < n_in; i++) {
        if (in_sizes[i] == NPTS * NCLS)    logits = (const float*)d_in[i];
        else if (in_sizes[i] == NPTS * NK) nbr    = (const int*)d_in[i];
        else if (in_sizes[i] == NPTS)      labels = (const int*)d_in[i];
    }
    float* out = (float*)d_out;

    softmax_kernel<<<(NPTS + 255) / 256, 256>>>(logits, RPAD);
    loss_kernel<<<2048, 256>>>(nbr, labels, out, RPAD * 2 /* bytes per row */);
}

// round 17
// speedup vs baseline: 1.2723x; 1.2723x over previous
#include <cuda_runtime.h>
#include <cuda_fp16.h>
#include <cstdint>

#define NPTS 500000
#define NCLS 20
#define RPAD 32      // padded row stride in halves (64 B rows, line-aligned)
#define NK   16

// fp16 probs table, 64B rows, 128B-aligned: 32 MB (L2-resident). Zero-initialized
// device global: padding halves [20,32) are never written and stay 0.
__device__ __align__(128) __half g_probs_h[(size_t)NPTS * RPAD];
__device__ float  g_acc[2];    // [0]=sum of mean_dist over valid pts, [1]=valid count
__device__ int    g_done = 0;

// Kernel 1: softmax, smem-staged coalesced loads, padded fp16 rows.
__global__ void softmax_kernel(const float* __restrict__ logits, int rstride) {
    __shared__ float tile[256 * 21];   // 21-float rows -> conflict-free column reads
    if (blockIdx.x == 0 && threadIdx.x == 0) {
        g_acc[0] = 0.0f;
        g_acc[1] = 0.0f;
        g_done   = 0;
    }
    const int rowBase = blockIdx.x * 256;
    const int rowsInBlock = min(256, NPTS - rowBase);
    if (rowsInBlock <= 0) return;

    const float4* s4 = reinterpret_cast<const float4*>(logits + (size_t)rowBase * NCLS);
    const int nvec = rowsInBlock * NCLS / 4;
    for (int i = threadIdx.x; i < nvec; i += 256) {
        float4 v = s4[i];
        int base = i * 4;
        int r = base / NCLS;
        int c = base - r * NCLS;
        float* d = &tile[r * 21 + c];
        d[0] = v.x; d[1] = v.y; d[2] = v.z; d[3] = v.w;
    }
    __syncthreads();

    const int n = rowBase + threadIdx.x;
    if (threadIdx.x >= rowsInBlock) return;
    float* f = &tile[threadIdx.x * 21];

    float m = f[0];
#pragma unroll
    for (int i = 1; i < NCLS; i++) m = fmaxf(m, f[i]);
    float s = 0.0f;
    float e[NCLS];
#pragma unroll
    for (int i = 0; i < NCLS; i++) { e[i] = __expf(f[i] - m); s += e[i]; }
    float inv = 1.0f / s;

    __half2 h[10];
#pragma unroll
    for (int i = 0; i < 10; i++)
        h[i] = __floats2half2_rn(e[2 * i] * inv, e[2 * i + 1] * inv);

    unsigned int* hw = reinterpret_cast<unsigned int*>(h);
    uint4* dst = reinterpret_cast<uint4*>(g_probs_h + (size_t)n * rstride);
    dst[0] = make_uint4(hw[0], hw[1], hw[2], hw[3]);
    dst[1] = make_uint4(hw[4], hw[5], hw[6], hw[7]);
    *reinterpret_cast<uint2*>(dst + 2) = make_uint2(hw[8], hw[9]);
}

// Kernel 2: warp-per-2-points gather, 8 rows per LDG.128, forced 32 regs,
// launched as EXACTLY ONE WAVE (148 SMs x 8 blocks = 1184 blocks) so no
// partial second wave dilutes occupancy.
// Lane layout: grp = lane>>2 (0..7), sub = lane&3; every lane loads uint4
// (bytes [16*sub,16*sub+16) of a 64B row); padding reads are zeros -> no lane
// predicate. Invalid neighbors self-redirect to the point's own row -> zero
// distance -> no validity predicate in the gather loop.
__global__ void __launch_bounds__(256, 8)
loss_kernel(const int* __restrict__ nbr,
            const int* __restrict__ labels,
            float* __restrict__ out, int rstrideB) {
    const int lane = threadIdx.x & 31;
    const int warpInBlock = threadIdx.x >> 5;
    const int warpsPerBlock = blockDim.x >> 5;
    const int gwarp = blockIdx.x * warpsPerBlock + warpInBlock;
    const int totalWarps = gridDim.x * warpsPerBlock;
    const int grp = lane >> 2;
    const int sub = lane & 3;
    const char* laneBase = reinterpret_cast<const char*>(g_probs_h) + 16 * sub;

    float accTot = 0.0f;
    float cnt    = 0.0f;
    const __half2 z2 = __float2half2_rn(0.f);

    for (int n0 = gwarp; n0 < NPTS; n0 += 2 * totalWarps) {
        const int n1 = n0 + totalWarps;
        const bool has1 = (n1 < NPTS);
        const int nS1 = min(n1, NPTS - 1);   // safe second point

        int lab0 = labels[n0];
        int lab1 = has1 ? labels[n1] : -1;

        // Full-warp neighbor-index load; premultiply; self-redirect invalid.
        const int myPt = (lane < 16) ? n0 : nS1;
        int idx = nbr[myPt * NK + (lane & 15)];
        bool nbValid = (idx >= 0);
        int myOff = (nbValid ? idx : myPt) * rstrideB;

        unsigned vm = __ballot_sync(0xFFFFFFFFu, nbValid);
        int nv0 = __popc(vm & 0xFFFFu);
        int nv1 = __popc(vm >> 16);

        // Own rows (uint4 per lane; tails read zero padding)
        uint4 p0 = *reinterpret_cast<const uint4*>(laneBase + n0 * rstrideB);
        uint4 p1 = *reinterpret_cast<const uint4*>(laneBase + nS1 * rstrideB);
        const __half2* ph0 = reinterpret_cast<const __half2*>(&p0);
        const __half2* ph1 = reinterpret_cast<const __half2*>(&p1);

        __half2 acc0 = z2, acc1 = z2;
#pragma unroll
        for (int s = 0; s < 2; s++) {
            int o0 = __shfl_sync(0xFFFFFFFFu, myOff, 8 * s + grp);
            int o1 = __shfl_sync(0xFFFFFFFFu, myOff, 16 + 8 * s + grp);
            uint4 q = *reinterpret_cast<const uint4*>(laneBase + o0);
            uint4 r = *reinterpret_cast<const uint4*>(laneBase + o1);
            const __half2* qh = reinterpret_cast<const __half2*>(&q);
            const __half2* rh = reinterpret_cast<const __half2*>(&r);
#pragma unroll
            for (int j = 0; j < 4; j++) {
                __half2 d0 = __hsub2(ph0[j], qh[j]);
                __half2 d1 = __hsub2(ph1[j], rh[j]);
                acc0 = __hfma2(d0, d0, acc0);
                acc1 = __hfma2(d1, d1, acc1);
            }
        }

        // Epilogue: validity enters only here (branchless).
        float inv0 = (lab0 != -1 && nv0 > 0) ? __frcp_rn((float)nv0) : 0.0f;
        float inv1 = (has1 && lab1 != -1 && nv1 > 0) ? __frcp_rn((float)nv1) : 0.0f;
        float2 a0 = __half22float2(acc0);
        float2 a1 = __half22float2(acc1);
        accTot = fmaf(a0.x + a0.y, inv0, accTot);
        accTot = fmaf(a1.x + a1.y, inv1, accTot);
        cnt += (lab0 != -1 ? 1.0f : 0.0f) + (has1 && lab1 != -1 ? 1.0f : 0.0f);
    }

    // One butterfly reduce per warp
#pragma unroll
    for (int o = 16; o > 0; o >>= 1)
        accTot += __shfl_xor_sync(0xFFFFFFFFu, accTot, o);

    // Block reduce -> one atomic pair per block
    __shared__ float sSum[32];
    __shared__ float sCnt[32];
    if (lane == 0) { sSum[warpInBlock] = accTot; sCnt[warpInBlock] = cnt; }
    __syncthreads();
    if (threadIdx.x == 0) {
        float bs = 0.0f, bc = 0.0f;
        for (int w = 0; w < warpsPerBlock; w++) { bs += sSum[w]; bc += sCnt[w]; }
        atomicAdd(&g_acc[0], bs);
        atomicAdd(&g_acc[1], bc);
        __threadfence();
        int t = atomicAdd(&g_done, 1);
        if (t == gridDim.x - 1) {
            out[0] = g_acc[0] / fmaxf(g_acc[1], 1.0f);  // LOSS_WEIGHT = 1.0
            g_done = 0;
        }
    }
}

extern "C" void kernel_launch(void* const* d_in, const int* in_sizes, int n_in,
                              void* d_out, int out_size) {
    const float* logits = nullptr;
    const int*   nbr    = nullptr;
    const int*   labels = nullptr;
    for (int i = 0; i < n_in; i++) {
        if (in_sizes[i] == NPTS * NCLS)    logits = (const float*)d_in[i];
        else if (in_sizes[i] == NPTS * NK) nbr    = (const int*)d_in[i];
        else if (in_sizes[i] == NPTS)      labels = (const int*)d_in[i];
    }
    float* out = (float*)d_out;

    softmax_kernel<<<(NPTS + 255) / 256, 256>>>(logits, RPAD);
    // Exactly one wave: 148 SMs x 8 blocks/SM.
    loss_kernel<<<148 * 8, 256>>>(nbr, labels, out, RPAD * 2 /* bytes per row */);
}